// round 15
// baseline (speedup 1.0000x reference)
#include <cuda_runtime.h>
#include <cstdint>

#define B_NO   8
#define T_DATA 5000
#define E_NO   2000
#define SUB_NO 20
#define HID_NO 10
#define SH_NO  200
#define T_NO   50
#define NCH    1600

#define PCH 10
#define NCHUNKS 500

typedef unsigned long long ull;

__device__ float g_CT[E_NO * SUB_NO];
__device__ float g_syn[B_NO * SUB_NO * T_DATA];
__device__ float g_conv[B_NO * SH_NO * (size_t)T_DATA];
__device__ float g_ybuf[B_NO * SH_NO * (size_t)T_DATA];

__device__ __forceinline__ ull pk2(float x, float y) {
    ull r;
    asm("mov.b64 %0, {%1, %2};" : "=l"(r) : "f"(x), "f"(y));
    return r;
}
__device__ __forceinline__ ull ffma2(ull a, ull b, ull c) {
    ull d;
    asm("fma.rn.f32x2 %0, %1, %2, %3;" : "=l"(d) : "l"(a), "l"(b), "l"(c));
    return d;
}
__device__ __forceinline__ ull add2(ull a, ull b) {
    ull d;
    asm("add.rn.f32x2 %0, %1, %2;" : "=l"(d) : "l"(a), "l"(b));
    return d;
}
__device__ __forceinline__ float2 upk2(ull v) {
    float2 f;
    asm("mov.b64 {%0, %1}, %2;" : "=f"(f.x), "=f"(f.y) : "l"(v));
    return f;
}
__device__ __forceinline__ float tanh_hw(float x) {
    float y;
    asm("tanh.approx.f32 %0, %1;" : "=f"(y) : "f"(x));
    return y;
}

// ---------- 1. prep ----------
__global__ void prep_kernel(const float* __restrict__ C, const float* __restrict__ Esc) {
    int i = blockIdx.x * 256 + threadIdx.x;
    if (i >= E_NO * SUB_NO) return;
    int e = i / SUB_NO, s = i % SUB_NO;
    g_CT[i] = C[s * E_NO + e] * expf(Esc[e]);
}

// ---------- 2. GEMM (R5-proven) ----------
#define ETILE 16
#define GROWS 128
#define GTHR  64
#define NTILE (E_NO / ETILE)

__global__ void __launch_bounds__(GTHR) gemm_kernel(const float* __restrict__ S_e) {
    __shared__ float sS[2][GROWS * 17];
    __shared__ float sC[2][ETILE * 20];
    const int b = blockIdx.y;
    const int t0 = blockIdx.x * GROWS;
    const int tid = threadIdx.x;
    const float* Sb = S_e + (size_t)b * T_DATA * E_NO;

    ull acc0[10], acc1[10];
#pragma unroll
    for (int s = 0; s < 10; s++) { acc0[s] = 0ull; acc1[s] = 0ull; }

    float4 pf[8];
    float pc[5];

#define LDG_TILE(E0)                                                        \
    {                                                                       \
        _Pragma("unroll")                                                   \
        for (int kk = 0; kk < 8; kk++) {                                    \
            int q = tid + kk * GTHR;                                        \
            int r = q >> 2, c4 = q & 3;                                     \
            int t = t0 + r;                                                 \
            pf[kk] = (t < T_DATA)                                           \
                ? *(const float4*)(Sb + (size_t)t * E_NO + (E0) + c4 * 4)   \
                : make_float4(0.f, 0.f, 0.f, 0.f);                          \
        }                                                                   \
        _Pragma("unroll")                                                   \
        for (int m = 0; m < 5; m++) pc[m] = g_CT[(E0) * 20 + tid * 5 + m];  \
    }

#define STS_TILE(BUF)                                                       \
    {                                                                       \
        _Pragma("unroll")                                                   \
        for (int kk = 0; kk < 8; kk++) {                                    \
            int q = tid + kk * GTHR;                                        \
            int r = q >> 2, c4 = q & 3;                                     \
            float* d = &sS[BUF][r * 17 + c4 * 4];                           \
            d[0] = pf[kk].x; d[1] = pf[kk].y;                               \
            d[2] = pf[kk].z; d[3] = pf[kk].w;                               \
        }                                                                   \
        _Pragma("unroll")                                                   \
        for (int m = 0; m < 5; m++) sC[BUF][tid * 5 + m] = pc[m];           \
    }

    LDG_TILE(0);
    STS_TILE(0);
    LDG_TILE(ETILE);
    __syncthreads();

    for (int it = 0; it < NTILE; it++) {
        const int cur = it & 1;
#pragma unroll
        for (int j = 0; j < ETILE; j++) {
            ull cp[10];
#pragma unroll
            for (int s = 0; s < 10; s++)
                cp[s] = *(const ull*)&sC[cur][j * 20 + 2 * s];
            float v0 = sS[cur][tid * 17 + j];
            float v1 = sS[cur][(tid + GTHR) * 17 + j];
            ull v0p = pk2(v0, v0), v1p = pk2(v1, v1);
#pragma unroll
            for (int s = 0; s < 10; s++) {
                acc0[s] = ffma2(v0p, cp[s], acc0[s]);
                acc1[s] = ffma2(v1p, cp[s], acc1[s]);
            }
        }
        if (it < NTILE - 1) {
            STS_TILE(cur ^ 1);
            if (it < NTILE - 2) LDG_TILE((it + 2) * ETILE);
            __syncthreads();
        }
    }

    int ta = t0 + tid;
    if (ta < T_DATA) {
#pragma unroll
        for (int s = 0; s < 10; s++) {
            float2 f = upk2(acc0[s]);
            g_syn[((size_t)b * SUB_NO + 2 * s)     * T_DATA + ta] = f.x;
            g_syn[((size_t)b * SUB_NO + 2 * s + 1) * T_DATA + ta] = f.y;
        }
    }
    int tb = t0 + GTHR + tid;
    if (tb < T_DATA) {
#pragma unroll
        for (int s = 0; s < 10; s++) {
            float2 f = upk2(acc1[s]);
            g_syn[((size_t)b * SUB_NO + 2 * s)     * T_DATA + tb] = f.x;
            g_syn[((size_t)b * SUB_NO + 2 * s + 1) * T_DATA + tb] = f.y;
        }
    }
}

// ---------- 3. depthwise causal conv (time-halved) ----------
#define CHALF 2500
__global__ void __launch_bounds__(256) conv_kernel(const float* __restrict__ W1) {
    const int bs = blockIdx.x;
    const int half = bs & 1;
    const int bsub = bs >> 1;
    const int b = bsub / SUB_NO, s = bsub % SUB_NO;
    const int t0 = half * CHALF;
    __shared__ float ss[T_NO - 1 + CHALF];
    const int tid = threadIdx.x;

    const float* sp = g_syn + ((size_t)b * SUB_NO + s) * T_DATA;
    for (int i = tid; i < T_NO - 1 + CHALF; i += 256) {
        int gt = t0 - (T_NO - 1) + i;
        ss[i] = (gt >= 0) ? sp[gt] : 0.0f;
    }
    __syncthreads();

    for (int h = 0; h < HID_NO; h++) {
        const int c = s * HID_NO + h;
        float w[T_NO];
#pragma unroll
        for (int i = 0; i < T_NO; i++) w[i] = __ldg(&W1[c * T_NO + i]);
        float* cp = g_conv + ((size_t)(b * SH_NO + c)) * T_DATA + t0;
        for (int t = tid; t < CHALF; t += 256) {
            float acc = 0.0f;
#pragma unroll
            for (int tau = 0; tau < T_NO; tau++)
                acc = fmaf(ss[T_NO - 1 + t - tau], w[tau], acc);
            cp[t] = acc;
        }
    }
}

// ---------- 4. recurrence: truncated-scatter A + ring-gather helpers ----------
// A: taps 1..19 truncated to 20-step window (70 FFMA2). Ring s_y depth 8.
// h1(MODE0): taps 20..29 + lag taps 11..19 (45 FMA).  h2(MODE1): taps 30..39
// + output stores.  h3(MODE2): taps 40..50 + conv + bias.
template<int TB0, int NT, int MODE>
__device__ __forceinline__ void run_helper(
    int lane, int ch, int c,
    const float* __restrict__ Wh, const float* __restrict__ b1,
    const float* __restrict__ W2l,
    ull (*s_y)[32][5], ull (*sp)[32][5])
{
    constexpr int BASE = TB0 / 10;
    float w[NT];
#pragma unroll
    for (int u = 0; u < NT; u++) w[u] = __ldg(&Wh[c * T_NO + TB0 - 1 + u]);
    float wl[9];
    if (MODE == 0) {
#pragma unroll
        for (int v = 0; v < 9; v++) wl[v] = __ldg(&Wh[c * T_NO + 10 + v]);
    }
    const float ew2  = (MODE == 1) ? expf(W2l[c]) : 0.0f;
    const float bias = (MODE == 2) ? b1[c] : 0.0f;
    const float* cv = g_conv + (size_t)ch * T_DATA;
    float* yo = g_ybuf + (size_t)ch * T_DATA;

    // zero ring slots: MODE0 -> 2,3 ; MODE1 -> 4,5 ; MODE2 -> 6,7
    {
        const int s0 = 2 + 2 * MODE;
#pragma unroll
        for (int q = 0; q < 5; q++) {
            s_y[s0][lane][q] = 0ull;
            s_y[s0 + 1][lane][q] = 0ull;
        }
    }
    float cn[10];
    if (MODE == 2) {
#pragma unroll
        for (int j = 0; j < 10; j += 2) {
            float2 t = *(const float2*)(cv + j);
            cn[j] = t.x; cn[j + 1] = t.y;
        }
    }
    __syncthreads();                               // B0

    for (int k = -1; k <= NCHUNKS - 2; k++) {
        float ya[20];                              // y[10*(k-BASE) + i]
        {
            const ull* r0 = &s_y[(k - BASE) & 7][lane][0];
            const ull* r1 = &s_y[(k - BASE + 1) & 7][lane][0];
#pragma unroll
            for (int q = 0; q < 5; q++) {
                float2 t = upk2(r0[q]); ya[2 * q] = t.x; ya[2 * q + 1] = t.y;
            }
#pragma unroll
            for (int q = 0; q < 5; q++) {
                float2 t = upk2(r1[q]); ya[10 + 2 * q] = t.x; ya[10 + 2 * q + 1] = t.y;
            }
        }
        float cf[10];
        if (MODE == 2) {                           // prefetch conv chunk k+2
            int nk = (k + 2 <= NCHUNKS - 1) ? (k + 2) : (NCHUNKS - 1);
#pragma unroll
            for (int j = 0; j < 10; j += 2) {
                float2 t = *(const float2*)(cv + nk * PCH + j);
                cf[j] = t.x; cf[j + 1] = t.y;
            }
        }
        if (MODE == 1 && k >= 1) {                 // store chunk k-1
            const ull* yr = &s_y[(k - 1) & 7][lane][0];
            float* yob = yo + (size_t)(k - 1) * PCH;
#pragma unroll
            for (int q = 0; q < 5; q++) {
                float2 t = upk2(yr[q]);
                *(float2*)(yob + 2 * q) = make_float2(ew2 * t.x, ew2 * t.y);
            }
        }
        float part[10];
        if (MODE == 2) {
#pragma unroll
            for (int j = 0; j < 10; j++) part[j] = cn[j] + bias;
        } else {
#pragma unroll
            for (int j = 0; j < 10; j++) part[j] = 0.0f;
        }
#pragma unroll
        for (int j = 0; j < 10; j++)
#pragma unroll
            for (int u = 0; u < NT; u++)
                part[j] = fmaf(ya[10 + j - u], w[u], part[j]);
        if (MODE == 0) {                           // lag taps 11..19 (45 FMA)
#pragma unroll
            for (int j = 0; j < 9; j++)
#pragma unroll
                for (int v = 0; v < 9; v++)
                    if (v >= j)
                        part[j] = fmaf(ya[19 + j - v], wl[v], part[j]);
        }
        ull* pw = &sp[(k + 1) & 1][lane][0];
#pragma unroll
        for (int q = 0; q < 5; q++) pw[q] = pk2(part[2 * q], part[2 * q + 1]);
        if (MODE == 2) {
#pragma unroll
            for (int j = 0; j < 10; j++) cn[j] = cf[j];
        }
        __syncthreads();                           // B1..B500
    }
    __syncthreads();                               // B501
    if (MODE == 1) {                               // final two chunks
#pragma unroll
        for (int cc = NCHUNKS - 2; cc <= NCHUNKS - 1; cc++) {
            const ull* yr = &s_y[cc & 7][lane][0];
            float* yob = yo + (size_t)cc * PCH;
#pragma unroll
            for (int q = 0; q < 5; q++) {
                float2 t = upk2(yr[q]);
                *(float2*)(yob + 2 * q) = make_float2(ew2 * t.x, ew2 * t.y);
            }
        }
    }
}

__global__ void __launch_bounds__(128, 1) recur_kernel(const float* __restrict__ Wh,
                                                       const float* __restrict__ b1,
                                                       const float* __restrict__ W2l) {
    __shared__ ull s_y[8][32][5];
    __shared__ ull s_p1[2][32][5];
    __shared__ ull s_p2[2][32][5];
    __shared__ ull s_p3[2][32][5];

    const int lane = threadIdx.x & 31;
    const int warp = threadIdx.x >> 5;
    const int ch = blockIdx.x * 32 + lane;
    const int c = ch % SH_NO;

    if (warp == 0) {
        float w[19];
#pragma unroll
        for (int i = 0; i < 19; i++) w[i] = __ldg(&Wh[c * T_NO + i]);
        const float w0 = w[0];
        ull wp0[9], wp1[9];
#pragma unroll
        for (int i = 0; i < 9; i++) {
            wp0[i] = pk2(w[2 * i], w[2 * i + 1]);
            wp1[i] = pk2(w[2 * i + 1], w[2 * i + 2]);
        }

        ull A2[10];                                // 20-step window
#pragma unroll
        for (int m = 0; m < 10; m++) A2[m] = 0ull;

        __syncthreads();                           // B0
        __syncthreads();                           // B1

        for (int k = 0; k < NCHUNKS; k++) {
            const ull* pp1 = &s_p1[k & 1][lane][0];
            const ull* pp2 = &s_p2[k & 1][lane][0];
            const ull* pp3 = &s_p3[k & 1][lane][0];
#pragma unroll
            for (int m = 0; m < 5; m++)
                A2[m] = add2(A2[m], add2(add2(pp1[m], pp2[m]), pp3[m]));

            ull* yrow = &s_y[k & 7][lane][0];
#pragma unroll
            for (int pp = 0; pp < 5; pp++) {
                float2 a = upk2(A2[pp]);
                float y0 = tanh_hw(a.x);
                float v1 = fmaf(y0, w0, a.y);
                float y1 = tanh_hw(v1);
                yrow[pp] = pk2(y0, y1);
                ull yy0 = pk2(y0, y0);
                ull yy1 = pk2(y1, y1);
#pragma unroll
                for (int i = 0; i < 9; i++)
                    if (i <= 8 - pp)
                        A2[pp + 1 + i] = ffma2(yy0, wp1[i],
                                         ffma2(yy1, wp0[i], A2[pp + 1 + i]));
            }
#pragma unroll
            for (int m = 0; m < 5; m++) A2[m] = A2[m + 5];
#pragma unroll
            for (int m = 5; m < 10; m++) A2[m] = 0ull;
            __syncthreads();                       // B2..B501
        }
    } else if (warp == 1) {
        run_helper<20, 10, 0>(lane, ch, c, Wh, b1, W2l, s_y, s_p1);
    } else if (warp == 2) {
        run_helper<30, 10, 1>(lane, ch, c, Wh, b1, W2l, s_y, s_p2);
    } else {
        run_helper<40, 11, 2>(lane, ch, c, Wh, b1, W2l, s_y, s_p3);
    }
}

// ---------- 5. reduce ----------
__global__ void __launch_bounds__(256) reduce_kernel(const float* __restrict__ V_o,
                                                     float* __restrict__ out) {
    int idx = blockIdx.x * 256 + threadIdx.x;
    if (idx >= B_NO * T_DATA) return;
    int b = idx / T_DATA, t = idx % T_DATA;
    const float* p = g_ybuf + (size_t)b * SH_NO * T_DATA + t;
    float a = V_o[0];
#pragma unroll 10
    for (int c = 0; c < SH_NO; c++) a += p[(size_t)c * T_DATA];
    out[idx] = a;
}

extern "C" void kernel_launch(void* const* d_in, const int* in_sizes, int n_in,
                              void* d_out, int out_size) {
    const float* S_e     = (const float*)d_in[0];
    const float* C_syn_e = (const float*)d_in[2];
    const float* E_scale = (const float*)d_in[4];
    const float* W1      = (const float*)d_in[6];
    const float* W2      = (const float*)d_in[7];
    const float* b1      = (const float*)d_in[8];
    const float* Wh      = (const float*)d_in[9];
    const float* V_o     = (const float*)d_in[11];
    float* out = (float*)d_out;

    prep_kernel<<<(E_NO * SUB_NO + 255) / 256, 256>>>(C_syn_e, E_scale);
    dim3 gg((T_DATA + GROWS - 1) / GROWS, B_NO);
    gemm_kernel<<<gg, GTHR>>>(S_e);
    conv_kernel<<<B_NO * SUB_NO * 2, 256>>>(W1);
    recur_kernel<<<NCH / 32, 128>>>(Wh, b1, W2);
    reduce_kernel<<<(B_NO * T_DATA + 255) / 256, 256>>>(V_o, out);
}

// round 16
// speedup vs baseline: 1.1521x; 1.1521x over previous
#include <cuda_runtime.h>
#include <cstdint>

#define B_NO   8
#define T_DATA 5000
#define E_NO   2000
#define SUB_NO 20
#define HID_NO 10
#define SH_NO  200
#define T_NO   50
#define NCH    1600

#define PCH 10
#define NCHUNKS 500

typedef unsigned long long ull;

__device__ float g_CT[E_NO * SUB_NO];
__device__ float g_syn[B_NO * SUB_NO * T_DATA];
__device__ float g_conv[B_NO * SH_NO * (size_t)T_DATA];
__device__ float g_ybuf[B_NO * SH_NO * (size_t)T_DATA];

__device__ __forceinline__ ull pk2(float x, float y) {
    ull r;
    asm("mov.b64 %0, {%1, %2};" : "=l"(r) : "f"(x), "f"(y));
    return r;
}
__device__ __forceinline__ ull ffma2(ull a, ull b, ull c) {
    ull d;
    asm("fma.rn.f32x2 %0, %1, %2, %3;" : "=l"(d) : "l"(a), "l"(b), "l"(c));
    return d;
}
__device__ __forceinline__ ull add2(ull a, ull b) {
    ull d;
    asm("add.rn.f32x2 %0, %1, %2;" : "=l"(d) : "l"(a), "l"(b));
    return d;
}
__device__ __forceinline__ float2 upk2(ull v) {
    float2 f;
    asm("mov.b64 {%0, %1}, %2;" : "=f"(f.x), "=f"(f.y) : "l"(v));
    return f;
}
__device__ __forceinline__ float tanh_hw(float x) {
    float y;
    asm("tanh.approx.f32 %0, %1;" : "=f"(y) : "f"(x));
    return y;
}

// ---------- 1. prep ----------
__global__ void prep_kernel(const float* __restrict__ C, const float* __restrict__ Esc) {
    int i = blockIdx.x * 256 + threadIdx.x;
    if (i >= E_NO * SUB_NO) return;
    int e = i / SUB_NO, s = i % SUB_NO;
    g_CT[i] = C[s * E_NO + e] * expf(Esc[e]);
}

// ---------- 2. GEMM (R5-proven) ----------
#define ETILE 16
#define GROWS 128
#define GTHR  64
#define NTILE (E_NO / ETILE)

__global__ void __launch_bounds__(GTHR) gemm_kernel(const float* __restrict__ S_e) {
    __shared__ float sS[2][GROWS * 17];
    __shared__ float sC[2][ETILE * 20];
    const int b = blockIdx.y;
    const int t0 = blockIdx.x * GROWS;
    const int tid = threadIdx.x;
    const float* Sb = S_e + (size_t)b * T_DATA * E_NO;

    ull acc0[10], acc1[10];
#pragma unroll
    for (int s = 0; s < 10; s++) { acc0[s] = 0ull; acc1[s] = 0ull; }

    float4 pf[8];
    float pc[5];

#define LDG_TILE(E0)                                                        \
    {                                                                       \
        _Pragma("unroll")                                                   \
        for (int kk = 0; kk < 8; kk++) {                                    \
            int q = tid + kk * GTHR;                                        \
            int r = q >> 2, c4 = q & 3;                                     \
            int t = t0 + r;                                                 \
            pf[kk] = (t < T_DATA)                                           \
                ? *(const float4*)(Sb + (size_t)t * E_NO + (E0) + c4 * 4)   \
                : make_float4(0.f, 0.f, 0.f, 0.f);                          \
        }                                                                   \
        _Pragma("unroll")                                                   \
        for (int m = 0; m < 5; m++) pc[m] = g_CT[(E0) * 20 + tid * 5 + m];  \
    }

#define STS_TILE(BUF)                                                       \
    {                                                                       \
        _Pragma("unroll")                                                   \
        for (int kk = 0; kk < 8; kk++) {                                    \
            int q = tid + kk * GTHR;                                        \
            int r = q >> 2, c4 = q & 3;                                     \
            float* d = &sS[BUF][r * 17 + c4 * 4];                           \
            d[0] = pf[kk].x; d[1] = pf[kk].y;                               \
            d[2] = pf[kk].z; d[3] = pf[kk].w;                               \
        }                                                                   \
        _Pragma("unroll")                                                   \
        for (int m = 0; m < 5; m++) sC[BUF][tid * 5 + m] = pc[m];           \
    }

    LDG_TILE(0);
    STS_TILE(0);
    LDG_TILE(ETILE);
    __syncthreads();

    for (int it = 0; it < NTILE; it++) {
        const int cur = it & 1;
#pragma unroll
        for (int j = 0; j < ETILE; j++) {
            ull cp[10];
#pragma unroll
            for (int s = 0; s < 10; s++)
                cp[s] = *(const ull*)&sC[cur][j * 20 + 2 * s];
            float v0 = sS[cur][tid * 17 + j];
            float v1 = sS[cur][(tid + GTHR) * 17 + j];
            ull v0p = pk2(v0, v0), v1p = pk2(v1, v1);
#pragma unroll
            for (int s = 0; s < 10; s++) {
                acc0[s] = ffma2(v0p, cp[s], acc0[s]);
                acc1[s] = ffma2(v1p, cp[s], acc1[s]);
            }
        }
        if (it < NTILE - 1) {
            STS_TILE(cur ^ 1);
            if (it < NTILE - 2) LDG_TILE((it + 2) * ETILE);
            __syncthreads();
        }
    }

    int ta = t0 + tid;
    if (ta < T_DATA) {
#pragma unroll
        for (int s = 0; s < 10; s++) {
            float2 f = upk2(acc0[s]);
            g_syn[((size_t)b * SUB_NO + 2 * s)     * T_DATA + ta] = f.x;
            g_syn[((size_t)b * SUB_NO + 2 * s + 1) * T_DATA + ta] = f.y;
        }
    }
    int tb = t0 + GTHR + tid;
    if (tb < T_DATA) {
#pragma unroll
        for (int s = 0; s < 10; s++) {
            float2 f = upk2(acc1[s]);
            g_syn[((size_t)b * SUB_NO + 2 * s)     * T_DATA + tb] = f.x;
            g_syn[((size_t)b * SUB_NO + 2 * s + 1) * T_DATA + tb] = f.y;
        }
    }
}

// ---------- 3. depthwise causal conv (time-halved) ----------
#define CHALF 2500
__global__ void __launch_bounds__(256) conv_kernel(const float* __restrict__ W1) {
    const int bs = blockIdx.x;
    const int half = bs & 1;
    const int bsub = bs >> 1;
    const int b = bsub / SUB_NO, s = bsub % SUB_NO;
    const int t0 = half * CHALF;
    __shared__ float ss[T_NO - 1 + CHALF];
    const int tid = threadIdx.x;

    const float* sp = g_syn + ((size_t)b * SUB_NO + s) * T_DATA;
    for (int i = tid; i < T_NO - 1 + CHALF; i += 256) {
        int gt = t0 - (T_NO - 1) + i;
        ss[i] = (gt >= 0) ? sp[gt] : 0.0f;
    }
    __syncthreads();

    for (int h = 0; h < HID_NO; h++) {
        const int c = s * HID_NO + h;
        float w[T_NO];
#pragma unroll
        for (int i = 0; i < T_NO; i++) w[i] = __ldg(&W1[c * T_NO + i]);
        float* cp = g_conv + ((size_t)(b * SH_NO + c)) * T_DATA + t0;
        for (int t = tid; t < CHALF; t += 256) {
            float acc = 0.0f;
#pragma unroll
            for (int tau = 0; tau < T_NO; tau++)
                acc = fmaf(ss[T_NO - 1 + t - tau], w[tau], acc);
            cp[t] = acc;
        }
    }
}

// ---------- 4. recurrence: balanced packed-gather pipeline ----------
// A: taps 1..19 triangular-truncated scatter (R15-proven).
// h1: taps 20..29 packed + lag taps 11..19 (scalar triangular).
// h2: taps 30..40 packed + conv + bias.
// h3: taps 41..50 packed + output stores.
// Ring s_y[8][32][5]: slot = chunk & 7.
// MODE: 0 = lag (h1), 1 = stores (h3), 2 = conv (h2)
template<int TB0, int NT, int BASE, int MODE>
__device__ __forceinline__ void run_helper(
    int lane, int ch, int c, int widx,
    const float* __restrict__ Wh, const float* __restrict__ b1,
    const float* __restrict__ W2l,
    ull (*s_y)[32][5], ull (*sp)[32][5])
{
    constexpr int G = 10 * BASE + 10 - TB0;        // ya idx = G + j - u, tau = TB0+u
    float w[NT];
#pragma unroll
    for (int u = 0; u < NT; u++) w[u] = __ldg(&Wh[c * T_NO + TB0 - 1 + u]);
    ull w2[NT];
#pragma unroll
    for (int u = 0; u < NT; u++) w2[u] = pk2(w[u], w[u]);
    float wl[9];
    if (MODE == 0) {
#pragma unroll
        for (int v = 0; v < 9; v++) wl[v] = __ldg(&Wh[c * T_NO + 10 + v]);   // tau=11+v
    }
    const float ew2  = (MODE == 1) ? expf(W2l[c]) : 0.0f;
    const float bias = (MODE == 2) ? b1[c] : 0.0f;
    const ull bias2  = pk2(bias, bias);
    const float* cv = g_conv + (size_t)ch * T_DATA;
    float* yo = g_ybuf + (size_t)ch * T_DATA;

    // zero ring slots 2*widx, 2*widx+1 (covers chunks -6..-1)
    {
        const int s0 = 2 * widx;
#pragma unroll
        for (int q = 0; q < 5; q++) {
            s_y[s0][lane][q] = 0ull;
            s_y[s0 + 1][lane][q] = 0ull;
        }
    }
    ull cn2[5];
    if (MODE == 2) {
#pragma unroll
        for (int q = 0; q < 5; q++) cn2[q] = *(const ull*)(cv + 2 * q);      // chunk 0
    }
    __syncthreads();                               // B0

    for (int k = -1; k <= NCHUNKS - 2; k++) {
        float ya[20];                              // y[10*(k-BASE) + i]
        {
            const ull* r0 = &s_y[(k - BASE) & 7][lane][0];
            const ull* r1 = &s_y[(k - BASE + 1) & 7][lane][0];
#pragma unroll
            for (int q = 0; q < 5; q++) {
                float2 t = upk2(r0[q]); ya[2 * q] = t.x; ya[2 * q + 1] = t.y;
            }
#pragma unroll
            for (int q = 0; q < 5; q++) {
                float2 t = upk2(r1[q]); ya[10 + 2 * q] = t.x; ya[10 + 2 * q + 1] = t.y;
            }
        }
        ull yp[19];                                // yp[i] = (ya[i], ya[i+1])
#pragma unroll
        for (int i = 0; i < 19; i++) yp[i] = pk2(ya[i], ya[i + 1]);

        ull cf2[5];
        if (MODE == 2) {                           // prefetch conv chunk k+2
            int nk = (k + 2 <= NCHUNKS - 1) ? (k + 2) : (NCHUNKS - 1);
#pragma unroll
            for (int q = 0; q < 5; q++) cf2[q] = *(const ull*)(cv + nk * PCH + 2 * q);
        }
        if (MODE == 1 && k >= 1) {                 // store chunk k-1
            const ull* yr = &s_y[(k - 1) & 7][lane][0];
            float* yob = yo + (size_t)(k - 1) * PCH;
#pragma unroll
            for (int q = 0; q < 5; q++) {
                float2 t = upk2(yr[q]);
                *(float2*)(yob + 2 * q) = make_float2(ew2 * t.x, ew2 * t.y);
            }
        }

        ull pt2[5];
        if (MODE == 2) {
#pragma unroll
            for (int q = 0; q < 5; q++) pt2[q] = add2(cn2[q], bias2);
        } else {
#pragma unroll
            for (int q = 0; q < 5; q++) pt2[q] = 0ull;
        }
#pragma unroll
        for (int u = 0; u < NT; u++)
#pragma unroll
            for (int q = 0; q < 5; q++)
                pt2[q] = ffma2(yp[G + 2 * q - u], w2[u], pt2[q]);

        ull* pw = &sp[(k + 1) & 1][lane][0];
        if (MODE == 0) {                           // lag taps 11..19, triangular
            float pf[10];
#pragma unroll
            for (int q = 0; q < 5; q++) {
                float2 t = upk2(pt2[q]); pf[2 * q] = t.x; pf[2 * q + 1] = t.y;
            }
#pragma unroll
            for (int j = 0; j < 9; j++)
#pragma unroll
                for (int v = 0; v < 9; v++)
                    if (v >= j)
                        pf[j] = fmaf(ya[19 + j - v], wl[v], pf[j]);
#pragma unroll
            for (int q = 0; q < 5; q++) pw[q] = pk2(pf[2 * q], pf[2 * q + 1]);
        } else {
#pragma unroll
            for (int q = 0; q < 5; q++) pw[q] = pt2[q];
        }
        if (MODE == 2) {
#pragma unroll
            for (int q = 0; q < 5; q++) cn2[q] = cf2[q];
        }
        __syncthreads();                           // B1..B500
    }
    __syncthreads();                               // B501
    if (MODE == 1) {                               // final two chunks
#pragma unroll
        for (int cc = NCHUNKS - 2; cc <= NCHUNKS - 1; cc++) {
            const ull* yr = &s_y[cc & 7][lane][0];
            float* yob = yo + (size_t)cc * PCH;
#pragma unroll
            for (int q = 0; q < 5; q++) {
                float2 t = upk2(yr[q]);
                *(float2*)(yob + 2 * q) = make_float2(ew2 * t.x, ew2 * t.y);
            }
        }
    }
}

__global__ void __launch_bounds__(128, 1) recur_kernel(const float* __restrict__ Wh,
                                                       const float* __restrict__ b1,
                                                       const float* __restrict__ W2l) {
    __shared__ ull s_y[8][32][5];
    __shared__ ull s_p1[2][32][5];
    __shared__ ull s_p2[2][32][5];
    __shared__ ull s_p3[2][32][5];

    const int lane = threadIdx.x & 31;
    const int warp = threadIdx.x >> 5;
    const int ch = blockIdx.x * 32 + lane;
    const int c = ch % SH_NO;

    if (warp == 0) {
        // ---- A: taps 1..19, truncated triangular scatter (R15-proven) ----
        float w[19];
#pragma unroll
        for (int i = 0; i < 19; i++) w[i] = __ldg(&Wh[c * T_NO + i]);
        const float w0 = w[0];
        ull wp0[9], wp1[9];
#pragma unroll
        for (int i = 0; i < 9; i++) {
            wp0[i] = pk2(w[2 * i], w[2 * i + 1]);
            wp1[i] = pk2(w[2 * i + 1], w[2 * i + 2]);
        }

        ull A2[10];                                // 20-step window
#pragma unroll
        for (int m = 0; m < 10; m++) A2[m] = 0ull;

        __syncthreads();                           // B0
        __syncthreads();                           // B1

        for (int k = 0; k < NCHUNKS; k++) {
            const ull* pp1 = &s_p1[k & 1][lane][0];
            const ull* pp2 = &s_p2[k & 1][lane][0];
            const ull* pp3 = &s_p3[k & 1][lane][0];
#pragma unroll
            for (int m = 0; m < 5; m++)
                A2[m] = add2(A2[m], add2(add2(pp1[m], pp2[m]), pp3[m]));

            ull* yrow = &s_y[k & 7][lane][0];
#pragma unroll
            for (int pp = 0; pp < 5; pp++) {
                float2 a = upk2(A2[pp]);
                float y0 = tanh_hw(a.x);
                float v1 = fmaf(y0, w0, a.y);
                float y1 = tanh_hw(v1);
                yrow[pp] = pk2(y0, y1);
                ull yy0 = pk2(y0, y0);
                ull yy1 = pk2(y1, y1);
#pragma unroll
                for (int i = 0; i < 9; i++)
                    if (i <= 8 - pp)
                        A2[pp + 1 + i] = ffma2(yy0, wp1[i],
                                         ffma2(yy1, wp0[i], A2[pp + 1 + i]));
            }
#pragma unroll
            for (int m = 0; m < 5; m++) A2[m] = A2[m + 5];
#pragma unroll
            for (int m = 5; m < 10; m++) A2[m] = 0ull;
            __syncthreads();                       // B2..B501
        }
    } else if (warp == 1) {
        run_helper<20, 10, 2, 0>(lane, ch, c, 1, Wh, b1, W2l, s_y, s_p1);
    } else if (warp == 2) {
        run_helper<30, 11, 3, 2>(lane, ch, c, 2, Wh, b1, W2l, s_y, s_p2);
    } else {
        run_helper<41, 10, 4, 1>(lane, ch, c, 3, Wh, b1, W2l, s_y, s_p3);
    }
}

// ---------- 5. reduce ----------
__global__ void __launch_bounds__(256) reduce_kernel(const float* __restrict__ V_o,
                                                     float* __restrict__ out) {
    int idx = blockIdx.x * 256 + threadIdx.x;
    if (idx >= B_NO * T_DATA) return;
    int b = idx / T_DATA, t = idx % T_DATA;
    const float* p = g_ybuf + (size_t)b * SH_NO * T_DATA + t;
    float a = V_o[0];
#pragma unroll 10
    for (int c = 0; c < SH_NO; c++) a += p[(size_t)c * T_DATA];
    out[idx] = a;
}

extern "C" void kernel_launch(void* const* d_in, const int* in_sizes, int n_in,
                              void* d_out, int out_size) {
    const float* S_e     = (const float*)d_in[0];
    const float* C_syn_e = (const float*)d_in[2];
    const float* E_scale = (const float*)d_in[4];
    const float* W1      = (const float*)d_in[6];
    const float* W2      = (const float*)d_in[7];
    const float* b1      = (const float*)d_in[8];
    const float* Wh      = (const float*)d_in[9];
    const float* V_o     = (const float*)d_in[11];
    float* out = (float*)d_out;

    prep_kernel<<<(E_NO * SUB_NO + 255) / 256, 256>>>(C_syn_e, E_scale);
    dim3 gg((T_DATA + GROWS - 1) / GROWS, B_NO);
    gemm_kernel<<<gg, GTHR>>>(S_e);
    conv_kernel<<<B_NO * SUB_NO * 2, 256>>>(W1);
    recur_kernel<<<NCH / 32, 128>>>(Wh, b1, W2);
    reduce_kernel<<<(B_NO * T_DATA + 255) / 256, 256>>>(V_o, out);
}